// round 3
// baseline (speedup 1.0000x reference)
#include <cuda_runtime.h>
#include <cstdint>

#define N_NODES 8192
#define DIM     512

// scratch (device globals: no allocation allowed)
__device__ float g_n1[N_NODES * DIM];          // 16 MB
__device__ float g_n2[N_NODES * DIM];          // 16 MB
__device__ float g_a1[(size_t)N_NODES * N_NODES];  // 256 MB raw n1@n2^T

// ---------------------------------------------------------------------------
// Bit-replication of XLA / Eigen fast tanh for f32:
//   |x| < 0.0004 -> x ; else x*P(x^2)/Q(x^2) on x clamped to +-7.90531...
// Explicit rn intrinsics so -use_fast_math / contraction cannot perturb it.
// ---------------------------------------------------------------------------
__device__ __forceinline__ float xla_tanh(float x) {
    float ax = fabsf(x);
    float xc = fminf(fmaxf(x, -7.90531110763549805f), 7.90531110763549805f);
    float x2 = __fmul_rn(xc, xc);
    float p = -2.76076847742355e-16f;
    p = fmaf(p, x2,  2.00018790482477e-13f);
    p = fmaf(p, x2, -8.60467152213735e-11f);
    p = fmaf(p, x2,  5.12229709037114e-08f);
    p = fmaf(p, x2,  1.48572235717979e-05f);
    p = fmaf(p, x2,  6.37261928875436e-04f);
    p = fmaf(p, x2,  4.89352455891786e-03f);
    float q =  1.19825839466702e-06f;
    q = fmaf(q, x2,  1.18534705686654e-04f);
    q = fmaf(q, x2,  2.26843463243900e-03f);
    q = fmaf(q, x2,  4.89352518554385e-03f);
    float r = __fdiv_rn(__fmul_rn(xc, p), q);
    return (ax < 0.0004f) ? x : r;
}

// tanh(3*x) with the multiply done exactly like the reference (fp32 rn mul)
__device__ __forceinline__ float tanh3_(float x) {
    return xla_tanh(__fmul_rn(3.0f, x));
}

// ---------------------------------------------------------------------------
// 128x128 tile staging: one 8-wide K slab of A,B into smem (transposed layout)
// ---------------------------------------------------------------------------
__device__ __forceinline__ void stage_slab(
    const float4 av, const float4 bv,
    float (&As)[8][128], float (&Bs)[8][128], int lrow, int lc)
{
    __syncthreads();
    As[lc + 0][lrow] = av.x;  As[lc + 1][lrow] = av.y;
    As[lc + 2][lrow] = av.z;  As[lc + 3][lrow] = av.w;
    Bs[lc + 0][lrow] = bv.x;  Bs[lc + 1][lrow] = bv.y;
    Bs[lc + 2][lrow] = bv.z;  Bs[lc + 3][lrow] = bv.w;
    __syncthreads();
}

// scalar FFMA slab (embed gemm): sequential-k single-accumulator per element
__device__ __forceinline__ void compute_slab(
    float (&As)[8][128], float (&Bs)[8][128],
    int tx, int ty, float (&acc)[8][8])
{
#pragma unroll
    for (int k = 0; k < 8; ++k) {
        float a[8], b[8];
        *(float4*)&a[0] = *(const float4*)&As[k][ty * 8];
        *(float4*)&a[4] = *(const float4*)&As[k][ty * 8 + 4];
        *(float4*)&b[0] = *(const float4*)&Bs[k][tx * 8];
        *(float4*)&b[4] = *(const float4*)&Bs[k][tx * 8 + 4];
#pragma unroll
        for (int r = 0; r < 8; ++r)
#pragma unroll
            for (int c = 0; c < 8; ++c)
                acc[r][c] = fmaf(a[r], b[c], acc[r][c]);
    }
}

// packed f32x2 FFMA2 slab (a1 gemm): same per-element rn rounding & k-order,
// 2x FFMA issue throughput. acc2[r][c2] holds columns (2*c2, 2*c2+1).
__device__ __forceinline__ void compute_slab_pk(
    float (&As)[8][128], float (&Bs)[8][128],
    int tx, int ty, unsigned long long (&acc2)[8][4])
{
#pragma unroll
    for (int k = 0; k < 8; ++k) {
        float a[8];
        *(float4*)&a[0] = *(const float4*)&As[k][ty * 8];
        *(float4*)&a[4] = *(const float4*)&As[k][ty * 8 + 4];
        unsigned long long b2[4];
        *(float4*)&b2[0] = *(const float4*)&Bs[k][tx * 8];      // (b0,b1),(b2,b3)
        *(float4*)&b2[2] = *(const float4*)&Bs[k][tx * 8 + 4];  // (b4,b5),(b6,b7)
#pragma unroll
        for (int r = 0; r < 8; ++r) {
            unsigned long long a2;
            asm("mov.b64 %0, {%1, %1};" : "=l"(a2) : "f"(a[r]));
#pragma unroll
            for (int c2 = 0; c2 < 4; ++c2)
                asm("fma.rn.f32x2 %0, %1, %2, %0;" : "+l"(acc2[r][c2]) : "l"(a2), "l"(b2[c2]));
        }
    }
}

// ---------------------------------------------------------------------------
// Kernel 1: n = xla_tanh(3*(emb[idx] @ W^T + b))   [8192 x 512]
// ---------------------------------------------------------------------------
__global__ __launch_bounds__(256) void embed_gemm(
    const float* __restrict__ emb, const float* __restrict__ W,
    const float* __restrict__ bias, const int* __restrict__ idx, int which)
{
    __shared__ __align__(16) float As[8][128];
    __shared__ __align__(16) float Bs[8][128];
    float* __restrict__ dst = which ? g_n2 : g_n1;

    const int bj = blockIdx.x, bi = blockIdx.y;
    const int tid = threadIdx.x;
    const int lrow = tid >> 1, lc = (tid & 1) * 4;
    const int tx = tid & 15, ty = tid >> 4;

    float acc[8][8];
#pragma unroll
    for (int r = 0; r < 8; ++r)
#pragma unroll
        for (int c = 0; c < 8; ++c) acc[r][c] = 0.0f;

    const int arow = idx[bi * 128 + lrow];
    const float* ap = emb + (size_t)arow * DIM + lc;
    const float* bp = W + (size_t)(bj * 128 + lrow) * DIM + lc;

    float4 av = *(const float4*)ap; ap += 8;
    float4 bv = *(const float4*)bp; bp += 8;
#pragma unroll 1
    for (int kt = 0; kt < DIM / 8; ++kt) {
        stage_slab(av, bv, As, Bs, lrow, lc);
        if (kt + 1 < DIM / 8) {
            av = *(const float4*)ap; ap += 8;
            bv = *(const float4*)bp; bp += 8;
        }
        compute_slab(As, Bs, tx, ty, acc);
    }

    const int gi0 = bi * 128 + ty * 8;
    const int gj0 = bj * 128 + tx * 8;
    float bb[8];
    *(float4*)&bb[0] = *(const float4*)&bias[gj0];
    *(float4*)&bb[4] = *(const float4*)&bias[gj0 + 4];
#pragma unroll
    for (int r = 0; r < 8; ++r) {
        float v[8];
#pragma unroll
        for (int c = 0; c < 8; ++c)
            v[c] = tanh3_(__fadd_rn(acc[r][c], bb[c]));   // (x@W^T + b) then *3, tanh
        *(float4*)&dst[(size_t)(gi0 + r) * DIM + gj0]     = make_float4(v[0], v[1], v[2], v[3]);
        *(float4*)&dst[(size_t)(gi0 + r) * DIM + gj0 + 4] = make_float4(v[4], v[5], v[6], v[7]);
    }
}

// ---------------------------------------------------------------------------
// Kernel 2: raw a1 = n1 @ n2^T  [8192 x 8192], sequential-k fma, packed f32x2
// ---------------------------------------------------------------------------
__global__ __launch_bounds__(256) void a1_gemm()
{
    __shared__ __align__(16) float As[8][128];
    __shared__ __align__(16) float Bs[8][128];

    const int bj = blockIdx.x, bi = blockIdx.y;
    const int tid = threadIdx.x;
    const int lrow = tid >> 1, lc = (tid & 1) * 4;
    const int tx = tid & 15, ty = tid >> 4;

    unsigned long long acc2[8][4];
#pragma unroll
    for (int r = 0; r < 8; ++r)
#pragma unroll
        for (int c2 = 0; c2 < 4; ++c2) acc2[r][c2] = 0ull;

    const float* ap = g_n1 + (size_t)(bi * 128 + lrow) * DIM + lc;
    const float* bp = g_n2 + (size_t)(bj * 128 + lrow) * DIM + lc;

    float4 av = *(const float4*)ap; ap += 8;
    float4 bv = *(const float4*)bp; bp += 8;
#pragma unroll 1
    for (int kt = 0; kt < DIM / 8; ++kt) {
        stage_slab(av, bv, As, Bs, lrow, lc);
        if (kt + 1 < DIM / 8) {
            av = *(const float4*)ap; ap += 8;
            bv = *(const float4*)bp; bp += 8;
        }
        compute_slab_pk(As, Bs, tx, ty, acc2);
    }

    const int gi0 = bi * 128 + ty * 8;
    const int gj0 = bj * 128 + tx * 8;
#pragma unroll
    for (int r = 0; r < 8; ++r) {
        *(float4*)&g_a1[(size_t)(gi0 + r) * N_NODES + gj0]     = *(float4*)&acc2[r][0];
        *(float4*)&g_a1[(size_t)(gi0 + r) * N_NODES + gj0 + 4] = *(float4*)&acc2[r][2];
    }
}

// ---------------------------------------------------------------------------
// Kernel 3: adj = xla_tanh(3*(a1 - a1^T))  elementwise with 32x32 tile transpose
// ---------------------------------------------------------------------------
__global__ __launch_bounds__(256) void adj_elem(float* __restrict__ out)
{
    __shared__ float s2[32][33];
    const int bi = blockIdx.y, bj = blockIdx.x;
    const int tx = threadIdx.x;        // 0..31
    const int ty = threadIdx.y;        // 0..7

    // transposed source tile: a1[bj*32 + r][bi*32 + tx]
#pragma unroll
    for (int r = ty; r < 32; r += 8)
        s2[r][tx] = g_a1[(size_t)(bj * 32 + r) * N_NODES + bi * 32 + tx];
    __syncthreads();

#pragma unroll
    for (int r = ty; r < 32; r += 8) {
        size_t o = (size_t)(bi * 32 + r) * N_NODES + bj * 32 + tx;
        float v = __fsub_rn(g_a1[o], s2[tx][r]);   // a1(i,j) - a1(j,i)
        out[o] = tanh3_(v);
    }
}

// ---------------------------------------------------------------------------
// Kernel 4: per-row exact top-k mask (radix select on |adj + 0.01*noise| bits),
//           jax tie-break (lowest index first). In-place on out.
// ---------------------------------------------------------------------------
__global__ __launch_bounds__(256) void topk_mask(
    float* __restrict__ out, const float* __restrict__ noise,
    const int* __restrict__ kptr)
{
    __shared__ unsigned int pb[N_NODES];
    __shared__ int hist[256];
    __shared__ unsigned int s_prefix;
    __shared__ int s_r, s_e;
    __shared__ int eq_idx[128];
    __shared__ int eq_cnt;

    const int row = blockIdx.x;
    const int tid = threadIdx.x;
    int k = 64;
    if (kptr) k = *kptr;
    if (k < 1) k = 1;
    if (k > N_NODES) k = N_NODES;

    float* __restrict__ orow = out + (size_t)row * N_NODES;
    const float* __restrict__ nrow = noise + (size_t)row * N_NODES;

    for (int j = tid; j < N_NODES; j += 256) {
        // exactly: abs(adj + 0.01*noise) as separate rn mul + rn add (no fma)
        float p = fabsf(__fadd_rn(orow[j], __fmul_rn(0.01f, nrow[j])));
        pb[j] = __float_as_uint(p);
    }
    __syncthreads();

    unsigned prefix = 0;
    int r = k;
    for (int shift = 24; shift >= 0; shift -= 8) {
        hist[tid] = 0;
        __syncthreads();
        const unsigned hm = (shift == 24) ? 0u : (0xFFFFFFFFu << (shift + 8));
        for (int j = tid; j < N_NODES; j += 256) {
            unsigned v = pb[j];
            if ((v & hm) == prefix) atomicAdd(&hist[(v >> shift) & 255], 1);
        }
        __syncthreads();
        if (tid == 0) {
            int cum = 0, b = 255;
            for (; b >= 0; --b) { cum += hist[b]; if (cum >= r) break; }
            if (b < 0) b = 0;
            s_r = r - (cum - hist[b]);
            s_prefix = prefix | ((unsigned)b << shift);
            s_e = hist[b];
        }
        __syncthreads();
        prefix = s_prefix;
        r = s_r;
    }

    const unsigned T = prefix;
    const int e = s_e;

    if (r < e) {  // tie at threshold: keep the r lowest-index equals
        if (tid == 0) eq_cnt = 0;
        __syncthreads();
        for (int j = tid; j < N_NODES; j += 256)
            if (pb[j] == T) {
                int p = atomicAdd(&eq_cnt, 1);
                if (p < 128) eq_idx[p] = j;
            }
        __syncthreads();
        if (tid == 0) {
            int cnt = eq_cnt < 128 ? eq_cnt : 128;
            for (int i = 1; i < cnt; ++i) {
                int v = eq_idx[i], q = i - 1;
                while (q >= 0 && eq_idx[q] > v) { eq_idx[q + 1] = eq_idx[q]; --q; }
                eq_idx[q + 1] = v;
            }
        }
        __syncthreads();
    }

    for (int j = tid; j < N_NODES; j += 256) {
        unsigned v = pb[j];
        bool sel = v > T;
        if (v == T) {
            if (r >= e) sel = true;
            else {
                for (int q = 0; q < r; ++q)
                    if (eq_idx[q] == j) { sel = true; break; }
            }
        }
        orow[j] = sel ? orow[j] : 0.0f;
    }
}

// ---------------------------------------------------------------------------
extern "C" void kernel_launch(void* const* d_in, const int* in_sizes, int n_in,
                              void* d_out, int out_size)
{
    const int*   idx   = (const int*)d_in[0];
    const float* emb1  = (const float*)d_in[1];
    const float* emb2  = (const float*)d_in[2];
    const float* l1w   = (const float*)d_in[3];
    const float* l1b   = (const float*)d_in[4];
    const float* l2w   = (const float*)d_in[5];
    const float* l2b   = (const float*)d_in[6];
    const float* noise = (const float*)d_in[7];
    const int*   kptr  = (n_in > 8) ? (const int*)d_in[8] : nullptr;
    float* out = (float*)d_out;

    dim3 g1(DIM / 128, N_NODES / 128);       // (4, 64)
    embed_gemm<<<g1, 256>>>(emb1, l1w, l1b, idx, 0);
    embed_gemm<<<g1, 256>>>(emb2, l2w, l2b, idx, 1);

    dim3 g2(N_NODES / 128, N_NODES / 128);   // (64, 64) full a1
    a1_gemm<<<g2, 256>>>();

    dim3 g3(N_NODES / 32, N_NODES / 32);     // (256, 256)
    adj_elem<<<g3, dim3(32, 8)>>>(out);

    topk_mask<<<N_NODES, 256>>>(out, noise, kptr);

    (void)in_sizes; (void)out_size;
}

// round 4
// speedup vs baseline: 1.0025x; 1.0025x over previous
#include <cuda_runtime.h>
#include <cstdint>

#define N_NODES 8192
#define DIM     512

// scratch (device globals: no allocation allowed)
__device__ float g_n1[N_NODES * DIM];              // 16 MB
__device__ float g_n2[N_NODES * DIM];              // 16 MB
__device__ float g_a1[(size_t)N_NODES * N_NODES];  // 256 MB raw n1@n2^T

// ---------------------------------------------------------------------------
// Bit-replication of XLA fast tanh f32 (verified bitmatch in round 3).
// ---------------------------------------------------------------------------
__device__ __forceinline__ float xla_tanh(float x) {
    float ax = fabsf(x);
    float xc = fminf(fmaxf(x, -7.90531110763549805f), 7.90531110763549805f);
    float x2 = __fmul_rn(xc, xc);
    float p = -2.76076847742355e-16f;
    p = fmaf(p, x2,  2.00018790482477e-13f);
    p = fmaf(p, x2, -8.60467152213735e-11f);
    p = fmaf(p, x2,  5.12229709037114e-08f);
    p = fmaf(p, x2,  1.48572235717979e-05f);
    p = fmaf(p, x2,  6.37261928875436e-04f);
    p = fmaf(p, x2,  4.89352455891786e-03f);
    float q =  1.19825839466702e-06f;
    q = fmaf(q, x2,  1.18534705686654e-04f);
    q = fmaf(q, x2,  2.26843463243900e-03f);
    q = fmaf(q, x2,  4.89352518554385e-03f);
    float r = __fdiv_rn(__fmul_rn(xc, p), q);
    return (ax < 0.0004f) ? x : r;
}

__device__ __forceinline__ float tanh3_(float x) {
    return xla_tanh(__fmul_rn(3.0f, x));
}

// ---------------------------------------------------------------------------
// slab staging (no syncs inside — caller controls barriers)
// ---------------------------------------------------------------------------
__device__ __forceinline__ void stage_to(
    float (&As)[8][128], float (&Bs)[8][128],
    const float4 av, const float4 bv, int lrow, int lc)
{
    As[lc + 0][lrow] = av.x;  As[lc + 1][lrow] = av.y;
    As[lc + 2][lrow] = av.z;  As[lc + 3][lrow] = av.w;
    Bs[lc + 0][lrow] = bv.x;  Bs[lc + 1][lrow] = bv.y;
    Bs[lc + 2][lrow] = bv.z;  Bs[lc + 3][lrow] = bv.w;
}

// scalar FFMA slab (embed gemm): sequential-k single-accumulator per element
__device__ __forceinline__ void compute_slab(
    float (&As)[8][128], float (&Bs)[8][128],
    int tx, int ty, float (&acc)[8][8])
{
#pragma unroll
    for (int k = 0; k < 8; ++k) {
        float a[8], b[8];
        *(float4*)&a[0] = *(const float4*)&As[k][ty * 8];
        *(float4*)&a[4] = *(const float4*)&As[k][ty * 8 + 4];
        *(float4*)&b[0] = *(const float4*)&Bs[k][tx * 8];
        *(float4*)&b[4] = *(const float4*)&Bs[k][tx * 8 + 4];
#pragma unroll
        for (int r = 0; r < 8; ++r)
#pragma unroll
            for (int c = 0; c < 8; ++c)
                acc[r][c] = fmaf(a[r], b[c], acc[r][c]);
    }
}

// packed f32x2 FFMA2 slab: same per-element rn rounding & sequential-k order
__device__ __forceinline__ void compute_slab_pk(
    float (&As)[8][128], float (&Bs)[8][128],
    int tx, int ty, unsigned long long (&acc2)[8][4])
{
#pragma unroll
    for (int k = 0; k < 8; ++k) {
        float a[8];
        *(float4*)&a[0] = *(const float4*)&As[k][ty * 8];
        *(float4*)&a[4] = *(const float4*)&As[k][ty * 8 + 4];
        unsigned long long b2[4];
        *(float4*)&b2[0] = *(const float4*)&Bs[k][tx * 8];
        *(float4*)&b2[2] = *(const float4*)&Bs[k][tx * 8 + 4];
#pragma unroll
        for (int r = 0; r < 8; ++r) {
            unsigned long long a2;
            asm("mov.b64 %0, {%1, %1};" : "=l"(a2) : "f"(a[r]));
#pragma unroll
            for (int c2 = 0; c2 < 4; ++c2)
                asm("fma.rn.f32x2 %0, %1, %2, %0;" : "+l"(acc2[r][c2]) : "l"(a2), "l"(b2[c2]));
        }
    }
}

// ---------------------------------------------------------------------------
// Kernel 1: both embeds fused via blockIdx.z
//   n = xla_tanh(3*(emb[idx] @ W^T + b))   [8192 x 512]
// ---------------------------------------------------------------------------
__global__ __launch_bounds__(256) void embed_gemm(
    const float* __restrict__ emb1, const float* __restrict__ emb2,
    const float* __restrict__ W1,   const float* __restrict__ W2,
    const float* __restrict__ b1,   const float* __restrict__ b2,
    const int* __restrict__ idx)
{
    __shared__ __align__(16) float As[2][8][128];
    __shared__ __align__(16) float Bs[2][8][128];

    const int which = blockIdx.z;
    const float* __restrict__ emb  = which ? emb2 : emb1;
    const float* __restrict__ W    = which ? W2   : W1;
    const float* __restrict__ bias = which ? b2   : b1;
    float* __restrict__ dst        = which ? g_n2 : g_n1;

    const int bj = blockIdx.x, bi = blockIdx.y;
    const int tid = threadIdx.x;
    const int lrow = tid >> 1, lc = (tid & 1) * 4;
    const int tx = tid & 15, ty = tid >> 4;

    float acc[8][8];
#pragma unroll
    for (int r = 0; r < 8; ++r)
#pragma unroll
        for (int c = 0; c < 8; ++c) acc[r][c] = 0.0f;

    const int arow = idx[bi * 128 + lrow];
    const float* ap = emb + (size_t)arow * DIM + lc;
    const float* bp = W + (size_t)(bj * 128 + lrow) * DIM + lc;

    float4 av = *(const float4*)ap; ap += 8;
    float4 bv = *(const float4*)bp; bp += 8;
    stage_to(As[0], Bs[0], av, bv, lrow, lc);
    __syncthreads();

#pragma unroll 1
    for (int kt = 0; kt < DIM / 8; kt += 2) {
        // even phase: compute buf0, prefetch & stage buf1
        av = *(const float4*)ap; bv = *(const float4*)bp; ap += 8; bp += 8;
        compute_slab(As[0], Bs[0], tx, ty, acc);
        stage_to(As[1], Bs[1], av, bv, lrow, lc);
        __syncthreads();
        // odd phase: compute buf1, prefetch & stage buf0 (except last)
        if (kt + 2 < DIM / 8) {
            av = *(const float4*)ap; bv = *(const float4*)bp; ap += 8; bp += 8;
        }
        compute_slab(As[1], Bs[1], tx, ty, acc);
        if (kt + 2 < DIM / 8) stage_to(As[0], Bs[0], av, bv, lrow, lc);
        __syncthreads();
    }

    const int gi0 = bi * 128 + ty * 8;
    const int gj0 = bj * 128 + tx * 8;
    float bb[8];
    *(float4*)&bb[0] = *(const float4*)&bias[gj0];
    *(float4*)&bb[4] = *(const float4*)&bias[gj0 + 4];
#pragma unroll
    for (int r = 0; r < 8; ++r) {
        float v[8];
#pragma unroll
        for (int c = 0; c < 8; ++c)
            v[c] = tanh3_(__fadd_rn(acc[r][c], bb[c]));
        *(float4*)&dst[(size_t)(gi0 + r) * DIM + gj0]     = make_float4(v[0], v[1], v[2], v[3]);
        *(float4*)&dst[(size_t)(gi0 + r) * DIM + gj0 + 4] = make_float4(v[4], v[5], v[6], v[7]);
    }
}

// ---------------------------------------------------------------------------
// Kernel 2: raw a1 = n1 @ n2^T, double-buffered, packed FFMA2, one sync/slab
// ---------------------------------------------------------------------------
__global__ __launch_bounds__(256) void a1_gemm()
{
    __shared__ __align__(16) float As[2][8][128];
    __shared__ __align__(16) float Bs[2][8][128];

    const int bj = blockIdx.x, bi = blockIdx.y;
    const int tid = threadIdx.x;
    const int lrow = tid >> 1, lc = (tid & 1) * 4;
    const int tx = tid & 15, ty = tid >> 4;

    unsigned long long acc2[8][4];
#pragma unroll
    for (int r = 0; r < 8; ++r)
#pragma unroll
        for (int c2 = 0; c2 < 4; ++c2) acc2[r][c2] = 0ull;

    const float* ap = g_n1 + (size_t)(bi * 128 + lrow) * DIM + lc;
    const float* bp = g_n2 + (size_t)(bj * 128 + lrow) * DIM + lc;

    float4 av = *(const float4*)ap; ap += 8;
    float4 bv = *(const float4*)bp; bp += 8;
    stage_to(As[0], Bs[0], av, bv, lrow, lc);
    __syncthreads();

#pragma unroll 1
    for (int kt = 0; kt < DIM / 8; kt += 2) {
        av = *(const float4*)ap; bv = *(const float4*)bp; ap += 8; bp += 8;
        compute_slab_pk(As[0], Bs[0], tx, ty, acc2);
        stage_to(As[1], Bs[1], av, bv, lrow, lc);
        __syncthreads();
        if (kt + 2 < DIM / 8) {
            av = *(const float4*)ap; bv = *(const float4*)bp; ap += 8; bp += 8;
        }
        compute_slab_pk(As[1], Bs[1], tx, ty, acc2);
        if (kt + 2 < DIM / 8) stage_to(As[0], Bs[0], av, bv, lrow, lc);
        __syncthreads();
    }

    const int gi0 = bi * 128 + ty * 8;
    const int gj0 = bj * 128 + tx * 8;
#pragma unroll
    for (int r = 0; r < 8; ++r) {
        *(float4*)&g_a1[(size_t)(gi0 + r) * N_NODES + gj0]     = *(float4*)&acc2[r][0];
        *(float4*)&g_a1[(size_t)(gi0 + r) * N_NODES + gj0 + 4] = *(float4*)&acc2[r][2];
    }
}

// ---------------------------------------------------------------------------
// Kernel 3: adj = xla_tanh(3*(a1 - a1^T)), 64x64 tiles, float4 both ways
// ---------------------------------------------------------------------------
__global__ __launch_bounds__(256) void adj_elem(float* __restrict__ out)
{
    __shared__ float s2[64][65];
    const int bi = blockIdx.y, bj = blockIdx.x;
    const int tid = threadIdx.x;
    const int cc = tid & 15;        // float4 column group (cols cc*4 .. cc*4+3)
    const int rr0 = tid >> 4;       // 0..15, rows stride 16

    // transposed-source tile: s2[c][r] = a1[bj*64 + r][bi*64 + c]
#pragma unroll
    for (int it = 0; it < 4; ++it) {
        int r = rr0 + it * 16;
        float4 v = *(const float4*)&g_a1[(size_t)(bj * 64 + r) * N_NODES + bi * 64 + cc * 4];
        s2[cc * 4 + 0][r] = v.x;
        s2[cc * 4 + 1][r] = v.y;
        s2[cc * 4 + 2][r] = v.z;
        s2[cc * 4 + 3][r] = v.w;
    }
    __syncthreads();

#pragma unroll
    for (int it = 0; it < 4; ++it) {
        int r = rr0 + it * 16;
        size_t o = (size_t)(bi * 64 + r) * N_NODES + bj * 64 + cc * 4;
        float4 d = *(const float4*)&g_a1[o];
        float4 w;
        w.x = tanh3_(__fsub_rn(d.x, s2[r][cc * 4 + 0]));
        w.y = tanh3_(__fsub_rn(d.y, s2[r][cc * 4 + 1]));
        w.z = tanh3_(__fsub_rn(d.z, s2[r][cc * 4 + 2]));
        w.w = tanh3_(__fsub_rn(d.w, s2[r][cc * 4 + 3]));
        *(float4*)&out[o] = w;
    }
}

// ---------------------------------------------------------------------------
// Kernel 4: per-row exact top-k mask (radix select, vectorized, warp-private
//           histograms, parallel suffix-scan bucket pick). In-place on out.
// ---------------------------------------------------------------------------
__global__ __launch_bounds__(256) void topk_mask(
    float* __restrict__ out, const float* __restrict__ noise,
    const int* __restrict__ kptr)
{
    __shared__ unsigned int pb[N_NODES];   // 32 KB pang bits
    __shared__ int whist[8][256];          // 8 KB per-warp hists
    __shared__ int hbin[256];
    __shared__ int suf[256];
    __shared__ unsigned int s_prefix;
    __shared__ int s_r, s_e;
    __shared__ int eq_idx[128];
    __shared__ int eq_cnt;

    const int row = blockIdx.x;
    const int tid = threadIdx.x;
    const int wid = tid >> 5;
    int k = 64;
    if (kptr) k = *kptr;
    if (k < 1) k = 1;
    if (k > N_NODES) k = N_NODES;

    float* __restrict__ orow = out + (size_t)row * N_NODES;
    const float* __restrict__ nrow = noise + (size_t)row * N_NODES;
    const float4* orow4 = (const float4*)orow;
    const float4* nrow4 = (const float4*)nrow;
    uint4* pb4 = (uint4*)pb;

    for (int j = tid; j < N_NODES / 4; j += 256) {
        float4 o = __ldg(&orow4[j]);
        float4 nz = __ldg(&nrow4[j]);
        uint4 v;
        v.x = __float_as_uint(fabsf(__fadd_rn(o.x, __fmul_rn(0.01f, nz.x))));
        v.y = __float_as_uint(fabsf(__fadd_rn(o.y, __fmul_rn(0.01f, nz.y))));
        v.z = __float_as_uint(fabsf(__fadd_rn(o.z, __fmul_rn(0.01f, nz.z))));
        v.w = __float_as_uint(fabsf(__fadd_rn(o.w, __fmul_rn(0.01f, nz.w))));
        pb4[j] = v;
    }
    __syncthreads();

    unsigned prefix = 0;
    int r = k;
#pragma unroll 1
    for (int shift = 24; shift >= 0; shift -= 8) {
        for (int i = tid; i < 8 * 256; i += 256) ((int*)whist)[i] = 0;
        __syncthreads();
        const unsigned hm = (shift == 24) ? 0u : (0xFFFFFFFFu << (shift + 8));
        int* myh = whist[wid];
        for (int j = tid; j < N_NODES / 4; j += 256) {
            uint4 v = pb4[j];
            if ((v.x & hm) == prefix) atomicAdd(&myh[(v.x >> shift) & 255], 1);
            if ((v.y & hm) == prefix) atomicAdd(&myh[(v.y >> shift) & 255], 1);
            if ((v.z & hm) == prefix) atomicAdd(&myh[(v.z >> shift) & 255], 1);
            if ((v.w & hm) == prefix) atomicAdd(&myh[(v.w >> shift) & 255], 1);
        }
        __syncthreads();
        {   // reduce 8 warps -> hbin, init suffix array
            int h = 0;
#pragma unroll
            for (int w = 0; w < 8; ++w) h += whist[w][tid];
            hbin[tid] = h;
            suf[tid] = h;
        }
        __syncthreads();
        // suffix sums: suf[b] = sum of bins b..255
#pragma unroll
        for (int d = 1; d < 256; d <<= 1) {
            int t = (tid + d < 256) ? suf[tid + d] : 0;
            __syncthreads();
            suf[tid] += t;
            __syncthreads();
        }
        {   // unique boundary bucket: suf[b] >= r > suf[b+1]
            int s = suf[tid];
            int snext = (tid < 255) ? suf[tid + 1] : 0;
            if (s >= r && snext < r) {
                s_prefix = prefix | ((unsigned)tid << shift);
                s_r = r - snext;
                s_e = hbin[tid];
            }
        }
        __syncthreads();
        prefix = s_prefix;
        r = s_r;
    }

    const unsigned T = prefix;   // exact k-th largest pang bits
    const int e = s_e;           // count equal to T

    if (r < e) {  // tie: keep r lowest-index equals (jax top_k order)
        if (tid == 0) eq_cnt = 0;
        __syncthreads();
        for (int j = tid; j < N_NODES; j += 256)
            if (pb[j] == T) {
                int p = atomicAdd(&eq_cnt, 1);
                if (p < 128) eq_idx[p] = j;
            }
        __syncthreads();
        if (tid == 0) {
            int cnt = eq_cnt < 128 ? eq_cnt : 128;
            for (int i = 1; i < cnt; ++i) {
                int v = eq_idx[i], q = i - 1;
                while (q >= 0 && eq_idx[q] > v) { eq_idx[q + 1] = eq_idx[q]; --q; }
                eq_idx[q + 1] = v;
            }
        }
        __syncthreads();
    }

    for (int j = tid; j < N_NODES / 4; j += 256) {
        uint4 v = pb4[j];
        float4 o = __ldg(&orow4[j]);
        float4 w;
        float* wp = (float*)&w;
        const float* op = (const float*)&o;
        const unsigned* vp = (const unsigned*)&v;
#pragma unroll
        for (int i = 0; i < 4; ++i) {
            unsigned vv = vp[i];
            bool sel = vv > T;
            if (vv == T) {
                if (r >= e) sel = true;
                else {
                    int jj = j * 4 + i;
                    for (int q = 0; q < r; ++q)
                        if (eq_idx[q] == jj) { sel = true; break; }
                }
            }
            wp[i] = sel ? op[i] : 0.0f;
        }
        ((float4*)orow)[j] = w;
    }
}

// ---------------------------------------------------------------------------
extern "C" void kernel_launch(void* const* d_in, const int* in_sizes, int n_in,
                              void* d_out, int out_size)
{
    const int*   idx   = (const int*)d_in[0];
    const float* emb1  = (const float*)d_in[1];
    const float* emb2  = (const float*)d_in[2];
    const float* l1w   = (const float*)d_in[3];
    const float* l1b   = (const float*)d_in[4];
    const float* l2w   = (const float*)d_in[5];
    const float* l2b   = (const float*)d_in[6];
    const float* noise = (const float*)d_in[7];
    const int*   kptr  = (n_in > 8) ? (const int*)d_in[8] : nullptr;
    float* out = (float*)d_out;

    dim3 g1(DIM / 128, N_NODES / 128, 2);    // (4, 64, 2) both embeds
    embed_gemm<<<g1, 256>>>(emb1, emb2, l1w, l2w, l1b, l2b, idx);

    dim3 g2(N_NODES / 128, N_NODES / 128);   // (64, 64)
    a1_gemm<<<g2, 256>>>();

    dim3 g3(N_NODES / 64, N_NODES / 64);     // (128, 128)
    adj_elem<<<g3, 256>>>(out);

    topk_mask<<<N_NODES, 256>>>(out, noise, kptr);

    (void)in_sizes; (void)out_size;
}

// round 5
// speedup vs baseline: 1.0714x; 1.0687x over previous
#include <cuda_runtime.h>
#include <cstdint>
#include <math.h>

#define N_NODES 8192
#define DIM     512
#define T1_PAD  132   // row stride (floats) for the 128x128 T1 stash

// scratch (device globals: no allocation allowed)
__device__ float g_n1[N_NODES * DIM];   // 16 MB
__device__ float g_n2[N_NODES * DIM];   // 16 MB

// ---------------------------------------------------------------------------
// Bit-replication of XLA fast tanh f32 (verified bitmatch rounds 3-4).
// Odd function bitwise: clamp/x2/p/q symmetric, sign rides the final mul/div.
// ---------------------------------------------------------------------------
__device__ __forceinline__ float xla_tanh(float x) {
    float ax = fabsf(x);
    float xc = fminf(fmaxf(x, -7.90531110763549805f), 7.90531110763549805f);
    float x2 = __fmul_rn(xc, xc);
    float p = -2.76076847742355e-16f;
    p = fmaf(p, x2,  2.00018790482477e-13f);
    p = fmaf(p, x2, -8.60467152213735e-11f);
    p = fmaf(p, x2,  5.12229709037114e-08f);
    p = fmaf(p, x2,  1.48572235717979e-05f);
    p = fmaf(p, x2,  6.37261928875436e-04f);
    p = fmaf(p, x2,  4.89352455891786e-03f);
    float q =  1.19825839466702e-06f;
    q = fmaf(q, x2,  1.18534705686654e-04f);
    q = fmaf(q, x2,  2.26843463243900e-03f);
    q = fmaf(q, x2,  4.89352518554385e-03f);
    float r = __fdiv_rn(__fmul_rn(xc, p), q);
    return (ax < 0.0004f) ? x : r;
}

__device__ __forceinline__ float tanh3_(float x) {
    return xla_tanh(__fmul_rn(3.0f, x));
}

// ---------------------------------------------------------------------------
// slab staging / packed FFMA2 compute on flat smem buffers
//   buffer b occupies floats [b*1024, b*1024+1024): layout [k][128]
// ---------------------------------------------------------------------------
__device__ __forceinline__ void stage_f(
    float* sA, float* sB, int buf,
    const float4 av, const float4 bv, int lrow, int lc)
{
    float* A = sA + buf * 1024;
    float* B = sB + buf * 1024;
    A[(lc + 0) * 128 + lrow] = av.x;  A[(lc + 1) * 128 + lrow] = av.y;
    A[(lc + 2) * 128 + lrow] = av.z;  A[(lc + 3) * 128 + lrow] = av.w;
    B[(lc + 0) * 128 + lrow] = bv.x;  B[(lc + 1) * 128 + lrow] = bv.y;
    B[(lc + 2) * 128 + lrow] = bv.z;  B[(lc + 3) * 128 + lrow] = bv.w;
}

// packed f32x2 FFMA2: per-lane rn rounding & sequential-k order identical to
// scalar fp32 fma chain (bit-verified). acc2[r][c2] = cols (2c2, 2c2+1).
__device__ __forceinline__ void compute_pk(
    const float* sA, const float* sB, int buf,
    int tx, int ty, unsigned long long (&acc2)[8][4])
{
    const float* A = sA + buf * 1024;
    const float* B = sB + buf * 1024;
#pragma unroll
    for (int k = 0; k < 8; ++k) {
        float a[8];
        *(float4*)&a[0] = *(const float4*)&A[k * 128 + ty * 8];
        *(float4*)&a[4] = *(const float4*)&A[k * 128 + ty * 8 + 4];
        unsigned long long b2[4];
        *(float4*)&b2[0] = *(const float4*)&B[k * 128 + tx * 8];
        *(float4*)&b2[2] = *(const float4*)&B[k * 128 + tx * 8 + 4];
#pragma unroll
        for (int r = 0; r < 8; ++r) {
            unsigned long long a2;
            asm("mov.b64 %0, {%1, %1};" : "=l"(a2) : "f"(a[r]));
#pragma unroll
            for (int c2 = 0; c2 < 4; ++c2)
                asm("fma.rn.f32x2 %0, %1, %2, %0;" : "+l"(acc2[r][c2]) : "l"(a2), "l"(b2[c2]));
        }
    }
}

// full 512-K double-buffered 128x128 tile GEMM: acc2 += Ablk @ Bblk^T
__device__ __forceinline__ void gemm_tile_pk(
    const float* __restrict__ Ablk, const float* __restrict__ Bblk,
    float* sA, float* sB, int lrow, int lc, int tx, int ty,
    unsigned long long (&acc2)[8][4])
{
    const float* ap = Ablk + (size_t)lrow * DIM + lc;
    const float* bp = Bblk + (size_t)lrow * DIM + lc;

    float4 av = *(const float4*)ap; ap += 8;
    float4 bv = *(const float4*)bp; bp += 8;
    stage_f(sA, sB, 0, av, bv, lrow, lc);
    __syncthreads();

#pragma unroll 1
    for (int kt = 0; kt < DIM / 8; kt += 2) {
        av = *(const float4*)ap; bv = *(const float4*)bp; ap += 8; bp += 8;
        compute_pk(sA, sB, 0, tx, ty, acc2);
        stage_f(sA, sB, 1, av, bv, lrow, lc);
        __syncthreads();
        if (kt + 2 < DIM / 8) {
            av = *(const float4*)ap; bv = *(const float4*)bp; ap += 8; bp += 8;
        }
        compute_pk(sA, sB, 1, tx, ty, acc2);
        if (kt + 2 < DIM / 8) stage_f(sA, sB, 0, av, bv, lrow, lc);
        __syncthreads();
    }
}

// ---------------------------------------------------------------------------
// Kernel 1: both embeds fused via blockIdx.z; packed FFMA2 mainloop
//   n = xla_tanh(3*(emb[idx] @ W^T + b))   [8192 x 512]
// ---------------------------------------------------------------------------
__global__ __launch_bounds__(256) void embed_gemm(
    const float* __restrict__ emb1, const float* __restrict__ emb2,
    const float* __restrict__ W1,   const float* __restrict__ W2,
    const float* __restrict__ b1,   const float* __restrict__ b2,
    const int* __restrict__ idx)
{
    __shared__ __align__(16) float sA[2 * 1024];
    __shared__ __align__(16) float sB[2 * 1024];

    const int which = blockIdx.z;
    const float* __restrict__ emb  = which ? emb2 : emb1;
    const float* __restrict__ W    = which ? W2   : W1;
    const float* __restrict__ bias = which ? b2   : b1;
    float* __restrict__ dst        = which ? g_n2 : g_n1;

    const int bj = blockIdx.x, bi = blockIdx.y;
    const int tid = threadIdx.x;
    const int lrow = tid >> 1, lc = (tid & 1) * 4;
    const int tx = tid & 15, ty = tid >> 4;

    unsigned long long acc2[8][4];
#pragma unroll
    for (int r = 0; r < 8; ++r)
#pragma unroll
        for (int c2 = 0; c2 < 4; ++c2) acc2[r][c2] = 0ull;

    const int arow = idx[bi * 128 + lrow];   // gather
    const float* Ablk = emb + (size_t)arow * DIM - (size_t)lrow * DIM; // gemm_tile adds lrow*DIM
    const float* Bblk = W + (size_t)(bj * 128) * DIM;

    gemm_tile_pk(Ablk, Bblk, sA, sB, lrow, lc, tx, ty, acc2);

    const int gi0 = bi * 128 + ty * 8;
    const int gj0 = bj * 128 + tx * 8;
    float bb[8];
    *(float4*)&bb[0] = *(const float4*)&bias[gj0];
    *(float4*)&bb[4] = *(const float4*)&bias[gj0 + 4];
#pragma unroll
    for (int r = 0; r < 8; ++r) {
        float accf[8];
#pragma unroll
        for (int c2 = 0; c2 < 4; ++c2) {
            float2 t = *(float2*)&acc2[r][c2];
            accf[2 * c2] = t.x; accf[2 * c2 + 1] = t.y;
        }
        float v[8];
#pragma unroll
        for (int c = 0; c < 8; ++c)
            v[c] = tanh3_(__fadd_rn(accf[c], bb[c]));
        *(float4*)&dst[(size_t)(gi0 + r) * DIM + gj0]     = make_float4(v[0], v[1], v[2], v[3]);
        *(float4*)&dst[(size_t)(gi0 + r) * DIM + gj0 + 4] = make_float4(v[4], v[5], v[6], v[7]);
    }
}

// ---------------------------------------------------------------------------
// Kernel 2 (fused): triangular tiles bi<=bj. Phase A: T1 = n1[bi]@n2[bj]^T
//   -> stash in smem. Phase B: T2 = n1[bj]@n2[bi]^T. Then
//   adj(bj-tile) = tanh3(T2 - T1^T) written directly; adj(bi-tile) = -adj^T.
// ---------------------------------------------------------------------------
__global__ __launch_bounds__(256) void fused_adj_gemm(float* __restrict__ out)
{
    extern __shared__ __align__(16) float smem_dyn[];
    float* sA  = smem_dyn;              // 2048 floats
    float* sB  = sA + 2 * 1024;         // 2048 floats
    float* T1s = sB + 2 * 1024;         // 128 * 132 floats

    // triangular decode: t -> (bi, bj), bi <= bj, cum(b) = b*(129-b)/2
    const int t = blockIdx.x;
    int bi = (int)((129.0 - sqrt(129.0 * 129.0 - 8.0 * (double)t)) * 0.5);
    if (bi < 0) bi = 0;
    while (bi < 63 && (bi + 1) * (129 - (bi + 1)) / 2 <= t) ++bi;
    while (bi > 0 && bi * (129 - bi) / 2 > t) --bi;
    const int bj = bi + (t - bi * (129 - bi) / 2);

    const int tid = threadIdx.x;
    const int lrow = tid >> 1, lc = (tid & 1) * 4;
    const int tx = tid & 15, ty = tid >> 4;

    unsigned long long acc2[8][4];
#pragma unroll
    for (int r = 0; r < 8; ++r)
#pragma unroll
        for (int c2 = 0; c2 < 4; ++c2) acc2[r][c2] = 0ull;

    // Phase A: T1 = n1[bi] @ n2[bj]^T
    gemm_tile_pk(g_n1 + (size_t)(bi * 128) * DIM, g_n2 + (size_t)(bj * 128) * DIM,
                 sA, sB, lrow, lc, tx, ty, acc2);

    // stash T1: rows i (bi-local) = ty*8+r, cols j (bj-local) = tx*8..
#pragma unroll
    for (int r = 0; r < 8; ++r) {
        *(float4*)&T1s[(ty * 8 + r) * T1_PAD + tx * 8]     = *(float4*)&acc2[r][0];
        *(float4*)&T1s[(ty * 8 + r) * T1_PAD + tx * 8 + 4] = *(float4*)&acc2[r][2];
    }

    if (bi != bj) {
        // Phase B: T2 = n1[bj] @ n2[bi]^T (fresh accumulator chain)
#pragma unroll
        for (int r = 0; r < 8; ++r)
#pragma unroll
            for (int c2 = 0; c2 < 4; ++c2) acc2[r][c2] = 0ull;
        gemm_tile_pk(g_n1 + (size_t)(bj * 128) * DIM, g_n2 + (size_t)(bi * 128) * DIM,
                     sA, sB, lrow, lc, tx, ty, acc2);
    }
    __syncthreads();   // T1s stores visible to all before transposed reads

    // acc2 now holds T2 (or T1 on the diagonal, which equals T2 bitwise).
    // rows j (bj-local) = ty*8+r, cols i (bi-local) = tx*8+c
    float v[8][8];
#pragma unroll
    for (int r = 0; r < 8; ++r) {
        float accf[8];
#pragma unroll
        for (int c2 = 0; c2 < 4; ++c2) {
            float2 tt = *(float2*)&acc2[r][c2];
            accf[2 * c2] = tt.x; accf[2 * c2 + 1] = tt.y;
        }
#pragma unroll
        for (int c = 0; c < 8; ++c) {
            float t1v = T1s[(tx * 8 + c) * T1_PAD + ty * 8 + r];   // T1(i, j)
            v[r][c] = tanh3_(__fsub_rn(accf[c], t1v));             // adj(J, I)
        }
    }

    // direct write: adj tile (bj, bi), coalesced
    {
        const int J0 = bj * 128 + ty * 8;
        const int I0 = bi * 128 + tx * 8;
#pragma unroll
        for (int r = 0; r < 8; ++r) {
            *(float4*)&out[(size_t)(J0 + r) * N_NODES + I0] =
                make_float4(v[r][0], v[r][1], v[r][2], v[r][3]);
            *(float4*)&out[(size_t)(J0 + r) * N_NODES + I0 + 4] =
                make_float4(v[r][4], v[r][5], v[r][6], v[r][7]);
        }
    }

    if (bi != bj) {
        __syncthreads();   // everyone done reading T1s
        // stash v as [j][i]
#pragma unroll
        for (int r = 0; r < 8; ++r) {
            *(float4*)&T1s[(ty * 8 + r) * T1_PAD + tx * 8]     = *(float4*)&v[r][0];
            *(float4*)&T1s[(ty * 8 + r) * T1_PAD + tx * 8 + 4] = *(float4*)&v[r][4];
        }
        __syncthreads();
        // mirror write: adj tile (bi, bj) = -adj(bj,bi)^T, coalesced
        const int I0 = bi * 128 + ty * 8;
        const int J0 = bj * 128 + tx * 8;
#pragma unroll
        for (int r = 0; r < 8; ++r) {
            float w[8];
#pragma unroll
            for (int c = 0; c < 8; ++c)
                w[c] = -T1s[(tx * 8 + c) * T1_PAD + ty * 8 + r];
            *(float4*)&out[(size_t)(I0 + r) * N_NODES + J0] =
                make_float4(w[0], w[1], w[2], w[3]);
            *(float4*)&out[(size_t)(I0 + r) * N_NODES + J0 + 4] =
                make_float4(w[4], w[5], w[6], w[7]);
        }
    }
}

// ---------------------------------------------------------------------------
// Kernel 3: per-row exact top-k mask, all-register (32 pang + 32 vals per
//           thread), radix select, jax tie-break. In-place on out.
// ---------------------------------------------------------------------------
__global__ __launch_bounds__(256) void topk_mask(
    float* __restrict__ out, const float* __restrict__ noise,
    const int* __restrict__ kptr)
{
    __shared__ int whist[8][256];
    __shared__ int hbin[256];
    __shared__ int suf[256];
    __shared__ unsigned int s_prefix;
    __shared__ int s_r, s_e;
    __shared__ int eq_idx[128];
    __shared__ int eq_cnt;

    const int row = blockIdx.x;
    const int tid = threadIdx.x;
    const int wid = tid >> 5;
    int k = 64;
    if (kptr) k = *kptr;
    if (k < 1) k = 1;
    if (k > N_NODES) k = N_NODES;

    float* __restrict__ orow = out + (size_t)row * N_NODES;
    const float4* o4 = (const float4*)orow;
    const float4* n4 = (const float4*)(noise + (size_t)row * N_NODES);

    unsigned pv[32];   // pang bits (non-negative floats: uint order == numeric)
    float    ov[32];   // adj values
#pragma unroll
    for (int i = 0; i < 8; ++i) {
        int j4 = tid + 256 * i;
        float4 o  = __ldg(&o4[j4]);
        float4 nz = __ldg(&n4[j4]);
        ov[i * 4 + 0] = o.x; ov[i * 4 + 1] = o.y; ov[i * 4 + 2] = o.z; ov[i * 4 + 3] = o.w;
        pv[i * 4 + 0] = __float_as_uint(fabsf(__fadd_rn(o.x, __fmul_rn(0.01f, nz.x))));
        pv[i * 4 + 1] = __float_as_uint(fabsf(__fadd_rn(o.y, __fmul_rn(0.01f, nz.y))));
        pv[i * 4 + 2] = __float_as_uint(fabsf(__fadd_rn(o.z, __fmul_rn(0.01f, nz.z))));
        pv[i * 4 + 3] = __float_as_uint(fabsf(__fadd_rn(o.w, __fmul_rn(0.01f, nz.w))));
    }

    unsigned prefix = 0;
    int r = k;
#pragma unroll 1
    for (int shift = 24; shift >= 0; shift -= 8) {
        for (int i = tid; i < 8 * 256; i += 256) ((int*)whist)[i] = 0;
        __syncthreads();
        const unsigned hm = (shift == 24) ? 0u : (0xFFFFFFFFu << (shift + 8));
        int* myh = whist[wid];
#pragma unroll
        for (int i = 0; i < 32; ++i) {
            unsigned vv = pv[i];
            if ((vv & hm) == prefix) atomicAdd(&myh[(vv >> shift) & 255], 1);
        }
        __syncthreads();
        {
            int h = 0;
#pragma unroll
            for (int w = 0; w < 8; ++w) h += whist[w][tid];
            hbin[tid] = h;
            suf[tid] = h;
        }
        __syncthreads();
#pragma unroll
        for (int d = 1; d < 256; d <<= 1) {
            int tt = (tid + d < 256) ? suf[tid + d] : 0;
            __syncthreads();
            suf[tid] += tt;
            __syncthreads();
        }
        {
            int s = suf[tid];
            int snext = (tid < 255) ? suf[tid + 1] : 0;
            if (s >= r && snext < r) {
                s_prefix = prefix | ((unsigned)tid << shift);
                s_r = r - snext;
                s_e = hbin[tid];
            }
        }
        __syncthreads();
        prefix = s_prefix;
        r = s_r;
    }

    const unsigned T = prefix;   // exact k-th largest pang bits
    const int e = s_e;           // count equal to T

    if (r < e) {  // tie at threshold: keep r lowest-index equals (jax order)
        if (tid == 0) eq_cnt = 0;
        __syncthreads();
#pragma unroll
        for (int i = 0; i < 32; ++i)
            if (pv[i] == T) {
                int jj = (tid + 256 * (i >> 2)) * 4 + (i & 3);
                int p = atomicAdd(&eq_cnt, 1);
                if (p < 128) eq_idx[p] = jj;
            }
        __syncthreads();
        if (tid == 0) {
            int cnt = eq_cnt < 128 ? eq_cnt : 128;
            for (int i = 1; i < cnt; ++i) {
                int v = eq_idx[i], q = i - 1;
                while (q >= 0 && eq_idx[q] > v) { eq_idx[q + 1] = eq_idx[q]; --q; }
                eq_idx[q + 1] = v;
            }
        }
        __syncthreads();
    }

#pragma unroll
    for (int i = 0; i < 8; ++i) {
        float w[4];
#pragma unroll
        for (int c = 0; c < 4; ++c) {
            unsigned vv = pv[i * 4 + c];
            bool sel = vv > T;
            if (vv == T) {
                if (r >= e) sel = true;
                else {
                    int jj = (tid + 256 * i) * 4 + c;
                    for (int q = 0; q < r; ++q)
                        if (eq_idx[q] == jj) { sel = true; break; }
                }
            }
            w[c] = sel ? ov[i * 4 + c] : 0.0f;
        }
        ((float4*)orow)[tid + 256 * i] = make_float4(w[0], w[1], w[2], w[3]);
    }
}

// ---------------------------------------------------------------------------
extern "C" void kernel_launch(void* const* d_in, const int* in_sizes, int n_in,
                              void* d_out, int out_size)
{
    const int*   idx   = (const int*)d_in[0];
    const float* emb1  = (const float*)d_in[1];
    const float* emb2  = (const float*)d_in[2];
    const float* l1w   = (const float*)d_in[3];
    const float* l1b   = (const float*)d_in[4];
    const float* l2w   = (const float*)d_in[5];
    const float* l2b   = (const float*)d_in[6];
    const float* noise = (const float*)d_in[7];
    const int*   kptr  = (n_in > 8) ? (const int*)d_in[8] : nullptr;
    float* out = (float*)d_out;

    dim3 g1(DIM / 128, N_NODES / 128, 2);    // (4, 64, 2) both embeds
    embed_gemm<<<g1, 256>>>(emb1, emb2, l1w, l2w, l1b, l2b, idx);

    const int fused_smem = (2 * 1024 + 2 * 1024 + 128 * T1_PAD) * (int)sizeof(float);
    cudaFuncSetAttribute(fused_adj_gemm,
                         cudaFuncAttributeMaxDynamicSharedMemorySize, fused_smem);
    fused_adj_gemm<<<2080, 256, fused_smem>>>(out);   // 64*65/2 triangular tiles

    topk_mask<<<N_NODES, 256>>>(out, noise, kptr);

    (void)in_sizes; (void)out_size;
}